// round 12
// baseline (speedup 1.0000x reference)
#include <cuda_runtime.h>
#include <cuda_bf16.h>
#include <cstdint>

#define N_NODES_MAX 100000
#define MASK_WORDS ((N_NODES_MAX + 31) / 32)
#define DSIGMA_DT (-0.0001f)
#define PHI_THRESH 0.3f
#define EPS 1e-8f

#define TPB 512

// Packed {pos.x, pos.y, pos.z, T}; accumulator {num.xyz, cnt} (zero at module
// load; re-zeroed in the finalize phase each execution); mask bitmap; flags.
__device__ float4 g_packed[N_NODES_MAX];
__device__ float4 g_acc[N_NODES_MAX];
__device__ unsigned g_mask[MASK_WORDS];
__device__ int g_idx_is64;
__device__ unsigned g_prep_done;   // returns to 0 every execution
__device__ unsigned g_bar_ctr;     // returns to 0 every execution
__device__ unsigned g_bar_gen;     // monotonic

__device__ __forceinline__ void grid_barrier(unsigned nblocks) {
    __syncthreads();
    if (threadIdx.x == 0) {
        volatile unsigned* genp = &g_bar_gen;
        unsigned gen = *genp;              // snapshot BEFORE arriving
        __threadfence();                   // publish this block's phase writes
        if (atomicAdd(&g_bar_ctr, 1u) == nblocks - 1u) {
            g_bar_ctr = 0;
            __threadfence();
            atomicAdd(&g_bar_gen, 1u);     // release
        } else {
            while (*genp == gen) { __nanosleep(32); }
        }
        __threadfence();                   // acquire
    }
    __syncthreads();
}

__device__ __forceinline__ void live_edge(int s, int d) {
    float4 a = __ldg(&g_packed[s]);
    float4 b = __ldg(&g_packed[d]);
    float dT = a.w - b.w;
    float px = a.x - b.x, py = a.y - b.y, pz = a.z - b.z;
    float w = dT / (px * px + py * py + pz * pz + EPS);
    float4* addr = &g_acc[d];
    asm volatile("red.global.add.v4.f32 [%0], {%1, %2, %3, %4};"
                 :: "l"(addr), "f"(w * px), "f"(w * py), "f"(w * pz), "f"(1.0f)
                 : "memory");
}

// Single fused kernel: prep (first n_prep_blocks slabs + flag) -> edge scatter
// (all blocks, after flag) -> grid barrier -> finalize + state reset.
// Avoids two ~5us small-kernel launch floors.
__global__ __launch_bounds__(TPB, 4) void fused_kernel(
        const float* __restrict__ x,
        const float* __restrict__ pos,
        const void* __restrict__ edge_index,
        float* __restrict__ out,
        int n_nodes, int n_edges, int mask_words,
        int n_prep_blocks, unsigned nblocks) {
    __shared__ unsigned smask[MASK_WORDS];
    const int tid = threadIdx.x;
    const int bid = blockIdx.x;

    // ── Phase A: prep (first n_prep_blocks blocks only) ──
    if (bid < n_prep_blocks) {
        int i = bid * TPB + tid;
        unsigned bit = 0;
        if (i < n_nodes) {
            float p0 = __ldg(&pos[i * 3 + 0]);
            float p1 = __ldg(&pos[i * 3 + 1]);
            float p2 = __ldg(&pos[i * 3 + 2]);
            float t  = __ldg(&x[i * 9 + 3]);
            float phi = __ldg(&x[i * 9 + 8]);
            g_packed[i] = make_float4(p0, p1, p2, t);
            bit = (fabsf(phi) < PHI_THRESH) ? 1u : 0u;
        }
        unsigned word = __ballot_sync(0xFFFFFFFFu, bit);
        if ((tid & 31) == 0 && i < n_nodes) g_mask[i >> 5] = word;

        if (bid == 0 && tid == 0) {
            // int64 LE with values < 2^31 => odd 32-bit words all zero.
            const unsigned int* w = (const unsigned int*)edge_index;
            unsigned int acc = 0;
            #pragma unroll
            for (int k = 0; k < 64; k++) acc |= w[2 * k + 1];
            g_idx_is64 = (acc == 0) ? 1 : 0;
        }
        __syncthreads();
        if (tid == 0) {
            __threadfence();
            atomicAdd(&g_prep_done, 1u);
        }
    }

    // ── wait for all prep slabs ──
    if (tid == 0) {
        volatile unsigned* done = &g_prep_done;
        while (*done < (unsigned)n_prep_blocks) { __nanosleep(32); }
        __threadfence();
    }
    __syncthreads();

    // ── stage mask bitmap in smem ──
    for (int w = tid; w < mask_words; w += TPB) smask[w] = g_mask[w];
    __syncthreads();

    // ── Phase B: edge scatter (R8 body, __ldcs index stream) ──
    const int S = gridDim.x * TPB;
    const int start = bid * TPB + tid;

    if (g_idx_is64) {
        const long long* ei = (const long long*)edge_index;
        for (int e = start; e < n_edges; e += S) {
            int d = (int)__ldcs(&ei[n_edges + e]);
            if ((smask[d >> 5] >> (d & 31)) & 1u) {
                int s = (int)__ldcs(&ei[e]);
                live_edge(s, d);
            }
        }
    } else {
        const int* ei = (const int*)edge_index;
        for (int e = start; e < n_edges; e += S) {
            int d = __ldcs(&ei[n_edges + e]);
            if ((smask[d >> 5] >> (d & 31)) & 1u) {
                int s = __ldcs(&ei[e]);
                live_edge(s, d);
            }
        }
    }

    grid_barrier(nblocks);

    // ── Phase C: finalize + reset (grid-stride over nodes) ──
    for (int i = start; i < n_nodes; i += S) {
        unsigned bit = (smask[i >> 5] >> (i & 31)) & 1u;
        float4 a = g_acc[i];
        float cnt = fmaxf(a.w, 1.0f);
        float s = bit ? (DSIGMA_DT / cnt) : 0.0f;
        out[i * 3 + 0] = s * a.x;
        out[i * 3 + 1] = s * a.y;
        out[i * 3 + 2] = s * a.z;
        // Only masked-in nodes ever receive REDs -> others stay zero.
        if (bit) g_acc[i] = make_float4(0.f, 0.f, 0.f, 0.f);
    }
    if (bid == 0 && tid == 0) g_prep_done = 0;
}

extern "C" void kernel_launch(void* const* d_in, const int* in_sizes, int n_in,
                              void* d_out, int out_size) {
    const float* x = (const float*)d_in[0];    // [N, 9]
    const float* pos = (const float*)d_in[1];  // [N, 3]
    const void* edge_index = d_in[2];          // [2, E] int32 or int64

    int n_nodes = in_sizes[1] / 3;
    int n_edges = in_sizes[2] / 2;
    int mask_words = (n_nodes + 31) / 32;
    int n_prep_blocks = (n_nodes + TPB - 1) / TPB;
    float* out = (float*)d_out;

    // All blocks must be co-resident for the spin barrier.
    int dev = 0;
    cudaGetDevice(&dev);
    int sms = 0;
    cudaDeviceGetAttribute(&sms, cudaDevAttrMultiProcessorCount, dev);
    int bps = 0;
    cudaOccupancyMaxActiveBlocksPerMultiprocessor(&bps, fused_kernel, TPB, 0);
    if (bps < 1) bps = 1;
    unsigned nblocks = (unsigned)(sms * bps);
    if (nblocks > 1184u) nblocks = 1184u;
    if (nblocks < (unsigned)n_prep_blocks) nblocks = (unsigned)n_prep_blocks;

    fused_kernel<<<nblocks, TPB>>>(x, pos, edge_index, out,
                                   n_nodes, n_edges, mask_words,
                                   n_prep_blocks, nblocks);
}